// round 3
// baseline (speedup 1.0000x reference)
#include <cuda_runtime.h>
#include <cstdint>

#define NPTS    300000
#define NCLS    20
#define KINST   100
#define SCORE_T 0.15f
#define VOTE_T  25
#define TPB     256

// NMS cluster geometry
#define NBC   8                    // cluster CTAs (portable max)
#define NTC   512                  // threads per CTA
#define NWARP (NTC / 32)
#define CPTC  26                   // candidate slots per thread
#define CAND_CTA (NTC * CPTC)      // 13312 per CTA
#define CAP  (NBC * CAND_CTA)      // 106496 total (nc ~ 102k, 17 sigma margin)

// ---------------- device scratch ------------------------------------------
__device__ float g_sx[NPTS], g_sy[NPTS], g_sz[NPTS];   // shifted coords
__device__ int   g_pan[NPTS];                          // semantic argmax
__device__ int   g_inst[NPTS];                         // instance id (fg only)
// compacted candidates
__device__ float g_cx[NPTS], g_cy[NPTS], g_cz[NPTS];
__device__ unsigned long long g_ckey[NPTS];
__device__ int   g_ncand;
// centers
__device__ float g_ctr[KINST * 3];
__device__ int   g_keep[KINST];
// (sem, inst) histogram
__device__ int   g_counts[100 * (KINST + 1)];

// key = (orderable(score) << 32) | (~orig_index): max key = max score,
// ties broken toward smallest original index (jnp.argmax). Nonzero for candidates.
__device__ __forceinline__ unsigned long long make_key(float s, unsigned idx) {
    return (((unsigned long long)(__float_as_uint(s) ^ 0x80000000u)) << 32)
         | (unsigned long long)(0xFFFFFFFFu - idx);
}
__device__ __forceinline__ unsigned long long pack2(float a, float b) {
    return (unsigned long long)__float_as_uint(a)
         | ((unsigned long long)__float_as_uint(b) << 32);
}
__device__ __forceinline__ uint32_t smem_u32(const void* p) {
    uint32_t a;
    asm("{ .reg .u64 t; cvta.to.shared.u64 t, %1; cvt.u32.u64 %0, t; }" : "=r"(a) : "l"(p));
    return a;
}
__device__ __forceinline__ unsigned long long dsm_ld_u64(uint32_t laddr, uint32_t rank) {
    uint32_t ra; unsigned long long v;
    asm volatile("mapa.shared::cluster.u32 %0, %1, %2;" : "=r"(ra) : "r"(laddr), "r"(rank));
    asm volatile("ld.shared::cluster.b64 %0, [%1];" : "=l"(v) : "r"(ra));
    return v;
}

// ---------------- kernel 0: reset cross-launch state ------------------------
__global__ void k_reset() {
    int t = threadIdx.x;
    if (t == 0) g_ncand = 0;
    for (int i = t; i < 100 * (KINST + 1); i += blockDim.x) g_counts[i] = 0;
}

// ---------------- kernel 1: semantics, shifted coords, candidate compaction -
__global__ void k_init(const float* __restrict__ xyz, const float* __restrict__ sem,
                       const float* __restrict__ off, const float* __restrict__ hmap) {
    int tid = blockIdx.x * blockDim.x + threadIdx.x;
    int stride = gridDim.x * blockDim.x;
    for (int i = tid; i < NPTS; i += stride) {
        const float* s = sem + (size_t)i * NCLS;
        float best = s[0]; int bp = 0;
#pragma unroll
        for (int j = 1; j < NCLS; j++) { float v = s[j]; if (v > best) { best = v; bp = j; } }
        g_pan[i] = bp;
        float sx = xyz[i * 3 + 0] + off[i * 3 + 0];
        float sy = xyz[i * 3 + 1] + off[i * 3 + 1];
        float sz = xyz[i * 3 + 2] + off[i * 3 + 2];
        g_sx[i] = sx; g_sy[i] = sy; g_sz[i] = sz;
        float h = hmap[i];
        if (bp >= 1 && bp <= 8 && h > SCORE_T) {
            int pos = atomicAdd(&g_ncand, 1);
            g_cx[pos] = sx; g_cy[pos] = sy; g_cz[pos] = sz;
            g_ckey[pos] = make_key(h, (unsigned)i);
        }
    }
}

// ---------------- kernel 2: cluster-persistent greedy vote-NMS --------------
// 8 CTAs x 512 thr in ONE cluster. Keys in SMEM, xyz in registers. Per round:
// reg/LDS sweep -> block reduce -> publish packed partial to own SMEM (double-
// buffered) -> cluster.sync -> warp0 reads 8 partials via DSMEM -> broadcast.
__global__ void __cluster_dims__(NBC, 1, 1) __launch_bounds__(NTC, 1)
k_nms(float* __restrict__ out) {
    extern __shared__ unsigned long long s_key[];      // CAND_CTA entries
    __shared__ unsigned long long s_par[2][5];         // packed partial, dbl-buffered
    __shared__ unsigned long long s_wk[NWARP];
    __shared__ float s_wx[NWARP], s_wy[NWARP], s_wz[NWARP];
    __shared__ int   s_wv[NWARP];
    __shared__ float s_sx[NWARP], s_sy[NWARP], s_sz[NWARP];
    __shared__ float s_b[3];
    __shared__ unsigned int s_bvalid;

    int rank = blockIdx.x;                             // == cluster rank (grid = 1 cluster)
    int t = threadIdx.x;
    int wid = t >> 5, lane = t & 31;
    int nc = g_ncand; if (nc > CAP) nc = CAP;
    int base = rank * CAND_CTA;

    float cx[CPTC], cy[CPTC], cz[CPTC];
#pragma unroll
    for (int j = 0; j < CPTC; j++) {
        int li = j * NTC + t;
        int gi = base + li;
        if (gi < nc) {
            s_key[li] = g_ckey[gi];
            cx[j] = g_cx[gi]; cy[j] = g_cy[gi]; cz[j] = g_cz[gi];
        } else s_key[li] = 0ull;
    }
    __syncthreads();

    bool valid = false;
    float px = 0.f, py = 0.f, pz = 0.f;

    for (int k = 0; k <= KINST; k++) {
        // ---- sweep: suppress+vote ball of winner(k-1), argmax for winner(k)
        unsigned long long lmax = 0ull;
        float mx = 0.f, my = 0.f, mz = 0.f;
        int lv = 0; float lx = 0.f, ly = 0.f, lz = 0.f;
#pragma unroll
        for (int j = 0; j < CPTC; j++) {
            int li = j * NTC + t;
            unsigned long long key = s_key[li];
            if (key) {
                float dx = cx[j] - px, dy = cy[j] - py, dz = cz[j] - pz;
                float d2 = fmaf(dx, dx, fmaf(dy, dy, dz * dz));
                if (valid && d2 < 1.0f) {
                    lv++; lx += cx[j]; ly += cy[j]; lz += cz[j];
                    s_key[li] = 0ull;
                } else if (key > lmax) {
                    lmax = key; mx = cx[j]; my = cy[j]; mz = cz[j];
                }
            }
        }
        // ---- warp reduce
        for (int o = 16; o; o >>= 1) {
            unsigned long long ok = __shfl_down_sync(0xffffffffu, lmax, o);
            float ox = __shfl_down_sync(0xffffffffu, mx, o);
            float oy = __shfl_down_sync(0xffffffffu, my, o);
            float oz = __shfl_down_sync(0xffffffffu, mz, o);
            if (ok > lmax) { lmax = ok; mx = ox; my = oy; mz = oz; }
            lv += __shfl_down_sync(0xffffffffu, lv, o);
            lx += __shfl_down_sync(0xffffffffu, lx, o);
            ly += __shfl_down_sync(0xffffffffu, ly, o);
            lz += __shfl_down_sync(0xffffffffu, lz, o);
        }
        if (lane == 0) {
            s_wk[wid] = lmax; s_wx[wid] = mx; s_wy[wid] = my; s_wz[wid] = mz;
            s_wv[wid] = lv; s_sx[wid] = lx; s_sy[wid] = ly; s_sz[wid] = lz;
        }
        __syncthreads();                               // (A)
        // ---- leader: combine warps, publish packed partial (own SMEM)
        if (t == 0) {
            unsigned long long bm = 0ull; float bx = 0.f, by = 0.f, bz = 0.f;
            int tv = 0; float tx = 0.f, ty = 0.f, tz = 0.f;
#pragma unroll
            for (int w = 0; w < NWARP; w++) {
                if (s_wk[w] > bm) { bm = s_wk[w]; bx = s_wx[w]; by = s_wy[w]; bz = s_wz[w]; }
                tv += s_wv[w]; tx += s_sx[w]; ty += s_sy[w]; tz += s_sz[w];
            }
            int p = k & 1;
            s_par[p][0] = bm;
            s_par[p][1] = pack2(bx, by);
            s_par[p][2] = (unsigned long long)__float_as_uint(bz)
                        | ((unsigned long long)(unsigned)tv << 32);
            s_par[p][3] = pack2(tx, ty);
            s_par[p][4] = pack2(tz, 0.f);
        }
        // ---- cluster barrier (arrive = release by t0 after its SMEM writes)
        asm volatile("barrier.cluster.arrive.aligned;" ::: "memory");
        asm volatile("barrier.cluster.wait.aligned;" ::: "memory");

        // ---- warp0: gather 8 partials via DSMEM, reduce, broadcast
        if (wid == 0) {
            unsigned long long bm = 0ull; float bx = 0.f, by = 0.f, bz = 0.f;
            int tv = 0; float tx = 0.f, ty = 0.f, tz = 0.f;
            if (lane < NBC) {
                uint32_t la = smem_u32(&s_par[k & 1][0]);
                unsigned long long q0 = dsm_ld_u64(la,      (uint32_t)lane);
                unsigned long long q1 = dsm_ld_u64(la + 8,  (uint32_t)lane);
                unsigned long long q2 = dsm_ld_u64(la + 16, (uint32_t)lane);
                unsigned long long q3 = dsm_ld_u64(la + 24, (uint32_t)lane);
                unsigned long long q4 = dsm_ld_u64(la + 32, (uint32_t)lane);
                bm = q0;
                bx = __uint_as_float((unsigned)(q1));       by = __uint_as_float((unsigned)(q1 >> 32));
                bz = __uint_as_float((unsigned)(q2));       tv = (int)(unsigned)(q2 >> 32);
                tx = __uint_as_float((unsigned)(q3));       ty = __uint_as_float((unsigned)(q3 >> 32));
                tz = __uint_as_float((unsigned)(q4));
            }
            for (int o = 16; o; o >>= 1) {
                unsigned long long ok = __shfl_down_sync(0xffffffffu, bm, o);
                float ox = __shfl_down_sync(0xffffffffu, bx, o);
                float oy = __shfl_down_sync(0xffffffffu, by, o);
                float oz = __shfl_down_sync(0xffffffffu, bz, o);
                if (ok > bm) { bm = ok; bx = ox; by = oy; bz = oz; }
                tv += __shfl_down_sync(0xffffffffu, tv, o);
                tx += __shfl_down_sync(0xffffffffu, tx, o);
                ty += __shfl_down_sync(0xffffffffu, ty, o);
                tz += __shfl_down_sync(0xffffffffu, tz, o);
            }
            if (lane == 0) {
                if (k >= 1 && rank == 0) {             // finalize center k-1
                    bool kp = valid && (tv >= VOTE_T);
                    float inv = 1.f / fmaxf((float)tv, 1.f);
                    float ccx = kp ? tx * inv : 0.f;
                    float ccy = kp ? ty * inv : 0.f;
                    float ccz = kp ? tz * inv : 0.f;
                    g_keep[k - 1] = kp ? 1 : 0;
                    g_ctr[(k - 1) * 3 + 0] = ccx; g_ctr[(k - 1) * 3 + 1] = ccy; g_ctr[(k - 1) * 3 + 2] = ccz;
                    out[(k - 1) * 3 + 0] = ccx; out[(k - 1) * 3 + 1] = ccy; out[(k - 1) * 3 + 2] = ccz;
                }
                s_bvalid = (bm != 0ull) ? 1u : 0u;
                s_b[0] = bx; s_b[1] = by; s_b[2] = bz;
            }
        }
        __syncthreads();                               // (B)
        valid = (s_bvalid != 0u);
        px = s_b[0]; py = s_b[1]; pz = s_b[2];
        // s_par slot k&1 next overwritten at round k+2, separated by 2 cluster
        // barriers from this round's remote reads -> race-free.
    }
}

// ---------------- kernel 3: nearest-center assignment + (sem,inst) histogram
__global__ void k_assign(float* __restrict__ out) {
    __shared__ float scx[KINST], scy[KINST], scz[KINST];
    __shared__ int shist[9 * (KINST + 1)];
    for (int t = threadIdx.x; t < KINST; t += blockDim.x) {
        if (g_keep[t]) { scx[t] = g_ctr[t * 3]; scy[t] = g_ctr[t * 3 + 1]; scz[t] = g_ctr[t * 3 + 2]; }
        else           { scx[t] = 1e18f; scy[t] = 1e18f; scz[t] = 1e18f; }
    }
    for (int t = threadIdx.x; t < 9 * (KINST + 1); t += blockDim.x) shist[t] = 0;
    __syncthreads();
    int tid = blockIdx.x * blockDim.x + threadIdx.x;
    int stride = gridDim.x * blockDim.x;
    for (int i = tid; i < NPTS; i += stride) {
        int p = g_pan[i];
        if (p < 1 || p > 8) { out[KINST * 3 + i] = (float)p; continue; }
        float sx = g_sx[i], sy = g_sy[i], sz = g_sz[i];
        int best = 0; float bd = 3.4e38f;
#pragma unroll 4
        for (int k = 0; k < KINST; k++) {
            float dx = sx - scx[k], dy = sy - scy[k], dz = sz - scz[k];
            float d2 = dx * dx + dy * dy + dz * dz;
            if (d2 < bd) { bd = d2; best = k; }       // strict < : first-index tiebreak
        }
        int inst = best + 1;
        g_inst[i] = inst;
        atomicAdd(&shist[p * (KINST + 1) + inst], 1);
    }
    __syncthreads();
    for (int t = threadIdx.x; t < 9 * (KINST + 1); t += blockDim.x) {
        int c = shist[t];
        if (c) atomicAdd(&g_counts[t], c);
    }
}

// ---------------- kernel 4: per-instance semantic argmax + final gather -----
__global__ void k_final(float* __restrict__ out) {
    __shared__ int ssem[KINST + 1];
    for (int t = threadIdx.x; t <= KINST; t += blockDim.x) {
        int best = g_counts[t]; int bp = 0;
        for (int p = 1; p <= 8; p++) {
            int c = g_counts[p * (KINST + 1) + t];
            if (c > best) { best = c; bp = p; }
        }
        ssem[t] = bp;
    }
    __syncthreads();
    int tid = blockIdx.x * blockDim.x + threadIdx.x;
    int stride = gridDim.x * blockDim.x;
    for (int i = tid; i < NPTS; i += stride) {
        int p = g_pan[i];
        if (p >= 1 && p <= 8) {
            int inst = g_inst[i];
            out[KINST * 3 + i] = (float)(ssem[inst] + (inst << 16));  // exact: < 2^24
        }
    }
}

extern "C" void kernel_launch(void* const* d_in, const int* in_sizes, int n_in,
                              void* d_out, int out_size) {
    const float* xyz  = (const float*)d_in[0];
    const float* sem  = (const float*)d_in[1];
    const float* off  = (const float*)d_in[2];
    const float* hmap = (const float*)d_in[3];
    float* out = (float*)d_out;
    static bool attr_done = false;
    if (!attr_done) {
        cudaFuncSetAttribute(k_nms, cudaFuncAttributeMaxDynamicSharedMemorySize,
                             CAND_CTA * sizeof(unsigned long long));
        attr_done = true;
    }
    k_reset <<<1, 256>>>();
    k_init  <<<1184, TPB>>>(xyz, sem, off, hmap);
    k_nms   <<<NBC, NTC, CAND_CTA * sizeof(unsigned long long)>>>(out);
    k_assign<<<1184, TPB>>>(out);
    k_final <<<1184, TPB>>>(out);
}

// round 4
// speedup vs baseline: 2.9734x; 2.9734x over previous
#include <cuda_runtime.h>
#include <cstdint>

#define NPTS    300000
#define NCLS    20
#define KINST   100
#define SCORE_T 0.15f
#define VOTE_T  25
#define TPB     256
#define NHIST   2048
#define TTOP    2048      // top-candidate sort size (power of 2)
#define TARGET  1536      // threshold target count (10x margin over ~150 needed)

// ---------------- device scratch ------------------------------------------
__device__ float g_sx[NPTS], g_sy[NPTS], g_sz[NPTS];   // shifted coords
__device__ int   g_pan[NPTS];                          // semantic argmax
__device__ int   g_inst[NPTS];                         // instance id (fg only)
// compacted candidates
__device__ float g_cx[NPTS], g_cy[NPTS], g_cz[NPTS];
__device__ unsigned long long g_ckey[NPTS];
__device__ int   g_ncand;
// top-candidate selection
__device__ int   g_hist[NHIST];
__device__ int   g_bstar;
__device__ unsigned long long g_tkey[TTOP];
__device__ int   g_ntop;
// winners (round order)
__device__ float g_wx[KINST], g_wy[KINST], g_wz[KINST];
__device__ int   g_wn;
// vote stats
__device__ int   g_votes[KINST];
__device__ float g_vsx[KINST], g_vsy[KINST], g_vsz[KINST];
// (sem, inst) histogram
__device__ int   g_counts[100 * (KINST + 1)];

// key = (orderable(score) << 32) | (~orig_index): max key = max score,
// ties -> smallest original index (jnp.argmax semantics). Nonzero for candidates.
__device__ __forceinline__ unsigned long long make_key(float s, unsigned idx) {
    return (((unsigned long long)(__float_as_uint(s) ^ 0x80000000u)) << 32)
         | (unsigned long long)(0xFFFFFFFFu - idx);
}
__device__ __forceinline__ float key_score(unsigned long long k) {
    return __uint_as_float((unsigned)(k >> 32) ^ 0x80000000u);
}
__device__ __forceinline__ int bucket_of(float s) {
    int b = (int)(s * (float)NHIST);
    return b < 0 ? 0 : (b >= NHIST ? NHIST - 1 : b);
}

// ---------------- kernel 0: reset cross-launch state ------------------------
__global__ void k_reset() {
    int t = threadIdx.x;
    if (t == 0) { g_ncand = 0; g_ntop = 0; g_wn = 0; }
    for (int i = t; i < NHIST; i += blockDim.x) g_hist[i] = 0;
    for (int i = t; i < TTOP; i += blockDim.x) g_tkey[i] = 0ull;
    for (int i = t; i < KINST; i += blockDim.x) {
        g_votes[i] = 0; g_vsx[i] = 0.f; g_vsy[i] = 0.f; g_vsz[i] = 0.f;
    }
    for (int i = t; i < 100 * (KINST + 1); i += blockDim.x) g_counts[i] = 0;
}

// ---------------- kernel 1: semantics, shifted coords, compaction, histogram
__global__ void k_init(const float* __restrict__ xyz, const float* __restrict__ sem,
                       const float* __restrict__ off, const float* __restrict__ hmap) {
    __shared__ int shist[NHIST];
    for (int i = threadIdx.x; i < NHIST; i += blockDim.x) shist[i] = 0;
    __syncthreads();
    int tid = blockIdx.x * blockDim.x + threadIdx.x;
    int stride = gridDim.x * blockDim.x;
    for (int i = tid; i < NPTS; i += stride) {
        const float* s = sem + (size_t)i * NCLS;
        float best = s[0]; int bp = 0;
#pragma unroll
        for (int j = 1; j < NCLS; j++) { float v = s[j]; if (v > best) { best = v; bp = j; } }
        g_pan[i] = bp;
        float sx = xyz[i * 3 + 0] + off[i * 3 + 0];
        float sy = xyz[i * 3 + 1] + off[i * 3 + 1];
        float sz = xyz[i * 3 + 2] + off[i * 3 + 2];
        g_sx[i] = sx; g_sy[i] = sy; g_sz[i] = sz;
        float h = hmap[i];
        if (bp >= 1 && bp <= 8 && h > SCORE_T) {
            int pos = atomicAdd(&g_ncand, 1);
            g_cx[pos] = sx; g_cy[pos] = sy; g_cz[pos] = sz;
            g_ckey[pos] = make_key(h, (unsigned)i);
            atomicAdd(&shist[bucket_of(h)], 1);
        }
    }
    __syncthreads();
    for (int i = threadIdx.x; i < NHIST; i += blockDim.x) {
        int c = shist[i];
        if (c) atomicAdd(&g_hist[i], c);
    }
}

// ---------------- kernel 2: pick score-threshold bucket ---------------------
__global__ void k_select() {
    __shared__ int sh[NHIST];
    for (int i = threadIdx.x; i < NHIST; i += blockDim.x) sh[i] = g_hist[i];
    __syncthreads();
    if (threadIdx.x == 0) {
        int acc = 0, b = NHIST - 1;
        for (; b > 0; b--) { acc += sh[b]; if (acc >= TARGET) break; }
        g_bstar = b;
    }
}

// ---------------- kernel 3: gather top candidates ---------------------------
__global__ void k_gather() {
    int i = blockIdx.x * blockDim.x + threadIdx.x;
    int nc = g_ncand;
    int bs = g_bstar;
    if (i < nc) {
        unsigned long long key = g_ckey[i];
        if (bucket_of(key_score(key)) >= bs) {
            int pos = atomicAdd(&g_ntop, 1);
            if (pos < TTOP) g_tkey[pos] = key;
        }
    }
}

// ---------------- kernel 4: single-block bitonic sort + greedy walk ---------
__global__ void __launch_bounds__(1024) k_sortwalk() {
    __shared__ unsigned long long s_key[TTOP];
    __shared__ float s_cx[TTOP], s_cy[TTOP], s_cz[TTOP];
    __shared__ unsigned s_rem[TTOP / 32];     // removed bitmask
    __shared__ float s_wx[KINST], s_wy[KINST], s_wz[KINST];
    __shared__ int s_i, s_nw;
    int t = threadIdx.x;

    for (int i = t; i < TTOP; i += 1024) s_key[i] = g_tkey[i];
    for (int i = t; i < TTOP / 32; i += 1024) s_rem[i] = 0u;
    if (t == 0) { s_i = 0; s_nw = 0; }
    __syncthreads();

    // bitonic sort, descending
    for (int kk = 2; kk <= TTOP; kk <<= 1) {
        for (int j = kk >> 1; j > 0; j >>= 1) {
            for (int i = t; i < TTOP; i += 1024) {
                int ixj = i ^ j;
                if (ixj > i) {
                    unsigned long long a = s_key[i], b = s_key[ixj];
                    bool sw = ((i & kk) == 0) ? (a < b) : (a > b);
                    if (sw) { s_key[i] = b; s_key[ixj] = a; }
                }
            }
            __syncthreads();
        }
    }
    // fetch xyz for sorted entries
    for (int i = t; i < TTOP; i += 1024) {
        unsigned long long key = s_key[i];
        if (key) {
            unsigned idx = 0xFFFFFFFFu - (unsigned)(key & 0xFFFFFFFFull);
            s_cx[i] = g_sx[idx]; s_cy[i] = g_sy[idx]; s_cz[i] = g_sz[idx];
        } else { s_cx[i] = 1e30f; s_cy[i] = 1e30f; s_cz[i] = 1e30f; }
    }

    // greedy walk: next unremoved in sorted order is a winner; mark its ball
    int wid = t >> 5, lane = t & 31;
    while (true) {
        __syncthreads();            // prior s_rem writes visible to scanner
        if (t == 0) {
            int i = s_i;
            while (i < TTOP) {
                unsigned w = s_rem[i >> 5];
                unsigned freebits = ~w & (0xFFFFFFFFu << (i & 31));
                if (freebits == 0u) { i = (i & ~31) + 32; continue; }
                i = (i & ~31) + __ffs(freebits) - 1;
                break;
            }
            s_i = i;
        }
        __syncthreads();
        int i = s_i, nw = s_nw;
        if (i >= TTOP || nw >= KINST) break;
        unsigned long long key = s_key[i];
        if (key == 0ull) break;                        // padding -> list exhausted
        float wx = s_cx[i], wy = s_cy[i], wz = s_cz[i];
        // mark coverage: thread t handles j = t and j = t + 1024
#pragma unroll
        for (int r = 0; r < 2; r++) {
            int j = t + r * 1024;
            float dx = s_cx[j] - wx, dy = s_cy[j] - wy, dz = s_cz[j] - wz;
            float d2 = fmaf(dx, dx, fmaf(dy, dy, dz * dz));
            unsigned bal = __ballot_sync(0xffffffffu, d2 < 1.0f);
            if (lane == 0 && bal) s_rem[wid + r * 32] |= bal;   // unique word per (warp,r)
        }
        if (t == 0) {
            s_wx[nw] = wx; s_wy[nw] = wy; s_wz[nw] = wz;
            s_nw = nw + 1; s_i = i + 1;
        }
    }
    __syncthreads();
    int nw = s_nw;
    if (t == 0) g_wn = nw;
    if (t < nw) { g_wx[t] = s_wx[t]; g_wy[t] = s_wy[t]; g_wz[t] = s_wz[t]; }
}

// ---------------- kernel 5: first-covering-winner vote stats ----------------
__global__ void k_votes() {
    __shared__ float swx[KINST], swy[KINST], swz[KINST];
    __shared__ int sv[KINST];
    __shared__ float ssx[KINST], ssy[KINST], ssz[KINST];
    int nw = g_wn;
    for (int k = threadIdx.x; k < nw; k += blockDim.x) {
        swx[k] = g_wx[k]; swy[k] = g_wy[k]; swz[k] = g_wz[k];
    }
    for (int k = threadIdx.x; k < KINST; k += blockDim.x) {
        sv[k] = 0; ssx[k] = 0.f; ssy[k] = 0.f; ssz[k] = 0.f;
    }
    __syncthreads();
    int i = blockIdx.x * blockDim.x + threadIdx.x;
    if (i < g_ncand) {
        float x = g_cx[i], y = g_cy[i], z = g_cz[i];
        int k0 = -1;
        for (int k = 0; k < nw; k++) {
            float dx = x - swx[k], dy = y - swy[k], dz = z - swz[k];
            float d2 = fmaf(dx, dx, fmaf(dy, dy, dz * dz));
            if (d2 < 1.0f) { k0 = k; break; }          // FIRST covering winner
        }
        if (k0 >= 0) {
            atomicAdd(&sv[k0], 1);
            atomicAdd(&ssx[k0], x); atomicAdd(&ssy[k0], y); atomicAdd(&ssz[k0], z);
        }
    }
    __syncthreads();
    for (int k = threadIdx.x; k < KINST; k += blockDim.x) {
        if (sv[k]) {
            atomicAdd(&g_votes[k], sv[k]);
            atomicAdd(&g_vsx[k], ssx[k]); atomicAdd(&g_vsy[k], ssy[k]); atomicAdd(&g_vsz[k], ssz[k]);
        }
    }
}

// ---------------- kernel 6: centers + nearest-center assignment + histogram -
__global__ void k_assign(float* __restrict__ out) {
    __shared__ float scx[KINST], scy[KINST], scz[KINST];
    __shared__ int shist[9 * (KINST + 1)];
    int nw = g_wn;
    for (int t = threadIdx.x; t < KINST; t += blockDim.x) {
        int v = g_votes[t];
        bool kp = (t < nw) && (v >= VOTE_T);
        float inv = 1.f / fmaxf((float)v, 1.f);
        float cx = kp ? g_vsx[t] * inv : 0.f;
        float cy = kp ? g_vsy[t] * inv : 0.f;
        float cz = kp ? g_vsz[t] * inv : 0.f;
        if (blockIdx.x == 0) {
            out[t * 3 + 0] = cx; out[t * 3 + 1] = cy; out[t * 3 + 2] = cz;
        }
        if (kp) { scx[t] = cx; scy[t] = cy; scz[t] = cz; }
        else    { scx[t] = 1e18f; scy[t] = 1e18f; scz[t] = 1e18f; }
    }
    for (int t = threadIdx.x; t < 9 * (KINST + 1); t += blockDim.x) shist[t] = 0;
    __syncthreads();
    int tid = blockIdx.x * blockDim.x + threadIdx.x;
    int stride = gridDim.x * blockDim.x;
    for (int i = tid; i < NPTS; i += stride) {
        int p = g_pan[i];
        if (p < 1 || p > 8) { out[KINST * 3 + i] = (float)p; continue; }
        float sx = g_sx[i], sy = g_sy[i], sz = g_sz[i];
        int best = 0; float bd = 3.4e38f;
#pragma unroll 4
        for (int k = 0; k < KINST; k++) {
            float dx = sx - scx[k], dy = sy - scy[k], dz = sz - scz[k];
            float d2 = dx * dx + dy * dy + dz * dz;
            if (d2 < bd) { bd = d2; best = k; }        // strict < : first-index tiebreak
        }
        int inst = best + 1;
        g_inst[i] = inst;
        atomicAdd(&shist[p * (KINST + 1) + inst], 1);
    }
    __syncthreads();
    for (int t = threadIdx.x; t < 9 * (KINST + 1); t += blockDim.x) {
        int c = shist[t];
        if (c) atomicAdd(&g_counts[t], c);
    }
}

// ---------------- kernel 7: per-instance semantic argmax + final gather -----
__global__ void k_final(float* __restrict__ out) {
    __shared__ int ssem[KINST + 1];
    for (int t = threadIdx.x; t <= KINST; t += blockDim.x) {
        int best = g_counts[t]; int bp = 0;
        for (int p = 1; p <= 8; p++) {
            int c = g_counts[p * (KINST + 1) + t];
            if (c > best) { best = c; bp = p; }
        }
        ssem[t] = bp;
    }
    __syncthreads();
    int tid = blockIdx.x * blockDim.x + threadIdx.x;
    int stride = gridDim.x * blockDim.x;
    for (int i = tid; i < NPTS; i += stride) {
        int p = g_pan[i];
        if (p >= 1 && p <= 8) {
            int inst = g_inst[i];
            out[KINST * 3 + i] = (float)(ssem[inst] + (inst << 16));  // exact: < 2^24
        }
    }
}

extern "C" void kernel_launch(void* const* d_in, const int* in_sizes, int n_in,
                              void* d_out, int out_size) {
    const float* xyz  = (const float*)d_in[0];
    const float* sem  = (const float*)d_in[1];
    const float* off  = (const float*)d_in[2];
    const float* hmap = (const float*)d_in[3];
    float* out = (float*)d_out;
    k_reset   <<<1, 256>>>();
    k_init    <<<1184, TPB>>>(xyz, sem, off, hmap);
    k_select  <<<1, 256>>>();
    k_gather  <<<(NPTS + TPB - 1) / TPB, TPB>>>();     // covers nc <= NPTS
    k_sortwalk<<<1, 1024>>>();
    k_votes   <<<(NPTS + TPB - 1) / TPB, TPB>>>();
    k_assign  <<<1184, TPB>>>(out);
    k_final   <<<1184, TPB>>>(out);
}